// round 9
// baseline (speedup 1.0000x reference)
#include <cuda_runtime.h>
#include <cstdint>

#define B_      256
#define SEQ_    128
#define HID_    1024
#define NB_     256
#define NL_     3
#define G_      2              // k-values per CTA in pass 1
#define KG_     (NB_/G_)       // 128 k-groups
#define CHUNKS_ 8              // b-chunks (split softmax)
#define BPC_    (B_/CHUNKS_)   // 32 b per chunk
#define DEPTH_  3              // cp.async pipeline depth (36 KB -> 5 CTA/SM)
#define RHS_    32             // h-splits for R@H partial work

// Scratch (static device arrays only — no cudaMalloc allowed)
__device__ float g_part_u[NB_][CHUNKS_][HID_];   // 8 MB
__device__ float g_part_m[NB_][CHUNKS_];
__device__ float g_part_z[NB_][CHUNKS_];
__device__ float g_u[NB_][HID_];                 // 1 MB
__device__ float g_RH[NL_][HID_];                // R_w @ H_w  (3 x 1024), atomic-accumulated
__device__ float g_act[B_][HID_];                // slow-path activations
__device__ int   g_flag;                         // 1 iff alpha == 1 everywhere

// spacer kernels so ncu's fixed window (4th launch) lands on k1_partials.
// k_zero also clears g_RH for this call's atomic accumulation (stream-ordered
// before k2's RH blocks; graph-capturable; no alloc).
__global__ void k_zero() {
    const int i = blockIdx.x * blockDim.x + threadIdx.x;
    if (i < NL_ * HID_) ((float*)g_RH)[i] = 0.f;
}
__global__ void k_noop() {}

// ---- cp.async helpers -------------------------------------------------------
__device__ __forceinline__ uint32_t smem_u32(const void* p) {
    return (uint32_t)__cvta_generic_to_shared(p);
}
__device__ __forceinline__ void cp_async16(uint32_t dst, const void* src) {
    asm volatile("cp.async.cg.shared.global [%0], [%1], 16;\n" :: "r"(dst), "l"(src));
}
__device__ __forceinline__ void cp_commit() {
    asm volatile("cp.async.commit_group;\n" ::: "memory");
}
template <int N>
__device__ __forceinline__ void cp_wait() {
    asm volatile("cp.async.wait_group %0;\n" :: "n"(N) : "memory");
}

// ---------------------------------------------------------------------------
// K1: cp.async-pipelined online softmax. CTA = (2 k's, 32 b's), 1024 CTAs.
// Stage (12 KB) = x row + 2 S rows; DEPTH_=3 stages (36 KB) -> 5 CTA/SM.
// Each thread copies ONLY the bytes it reads, so cp.async completion needs
// no barrier; the single barrier per b is the score reduce.
// ---------------------------------------------------------------------------
__global__ __launch_bounds__(256) void k1_partials(
    const float* __restrict__ ee, const float* __restrict__ S)
{
    extern __shared__ float sm[];         // [DEPTH_][3][HID_]
    __shared__ float2 red[2][8];          // double-buffered warp partials

    const int t     = threadIdx.x;
    const int w     = t >> 5;
    const int lane  = t & 31;
    const int kg    = blockIdx.x;
    const int c     = blockIdx.y;
    const int b0    = c * BPC_;
    const int kbase = kg * G_;
    const int h4    = t * 4;

    auto issue = [&](int stage, int b) {
        float* dst = sm + stage * 3 * HID_;
        cp_async16(smem_u32(dst + h4),
                   ee + (size_t)b * SEQ_ * HID_ + h4);
        cp_async16(smem_u32(dst + HID_ + h4),
                   S + ((size_t)b * NB_ + kbase) * HID_ + h4);
        cp_async16(smem_u32(dst + 2 * HID_ + h4),
                   S + ((size_t)b * NB_ + kbase + 1) * HID_ + h4);
    };

#pragma unroll
    for (int d = 0; d < DEPTH_; d++) { issue(d, b0 + d); cp_commit(); }

    float4 acc0 = make_float4(0.f, 0.f, 0.f, 0.f);
    float4 acc1 = make_float4(0.f, 0.f, 0.f, 0.f);
    float m0 = -3.0e38f, m1 = -3.0e38f, z0 = 0.f, z1 = 0.f;

    int stage = 0;
    for (int bi = 0; bi < BPC_; bi++) {
        cp_wait<DEPTH_ - 1>();            // stage for bi complete (per-thread)

        float* st = sm + stage * 3 * HID_;
        const float4 xv = *(const float4*)(st + h4);
        const float4 s0 = *(const float4*)(st + HID_ + h4);
        const float4 s1 = *(const float4*)(st + 2 * HID_ + h4);

        // refill this stage immediately (values already in regs; thread-own slots)
        const int bn = bi + DEPTH_;
        if (bn < BPC_) issue(stage, b0 + bn);
        cp_commit();                      // uniform group count even when empty
        if (++stage == DEPTH_) stage = 0;

        // two partial dots
        float dx = xv.x*s0.x + xv.y*s0.y + xv.z*s0.z + xv.w*s0.w;
        float dy = xv.x*s1.x + xv.y*s1.y + xv.z*s1.z + xv.w*s1.w;
#pragma unroll
        for (int off = 16; off > 0; off >>= 1) {
            dx += __shfl_xor_sync(0xffffffffu, dx, off);
            dy += __shfl_xor_sync(0xffffffffu, dy, off);
        }
        if (lane == 0) red[bi & 1][w] = make_float2(dx, dy);
        __syncthreads();
        float sc0 = 0.f, sc1 = 0.f;
#pragma unroll
        for (int w2 = 0; w2 < 8; w2++) {
            const float2 r = red[bi & 1][w2];
            sc0 += r.x; sc1 += r.y;
        }

        // online softmax updates (block-uniform branches)
        if (sc0 > m0) {
            const float cf = __expf(m0 - sc0);
            z0 = z0 * cf + 1.f;
            acc0.x = acc0.x * cf + s0.x; acc0.y = acc0.y * cf + s0.y;
            acc0.z = acc0.z * cf + s0.z; acc0.w = acc0.w * cf + s0.w;
            m0 = sc0;
        } else {
            const float wg = __expf(sc0 - m0);
            z0 += wg;
            acc0.x += wg * s0.x; acc0.y += wg * s0.y;
            acc0.z += wg * s0.z; acc0.w += wg * s0.w;
        }
        if (sc1 > m1) {
            const float cf = __expf(m1 - sc1);
            z1 = z1 * cf + 1.f;
            acc1.x = acc1.x * cf + s1.x; acc1.y = acc1.y * cf + s1.y;
            acc1.z = acc1.z * cf + s1.z; acc1.w = acc1.w * cf + s1.w;
            m1 = sc1;
        } else {
            const float wg = __expf(sc1 - m1);
            z1 += wg;
            acc1.x += wg * s1.x; acc1.y += wg * s1.y;
            acc1.z += wg * s1.z; acc1.w += wg * s1.w;
        }
    }

    *(float4*)&g_part_u[kbase + 0][c][h4] = acc0;
    *(float4*)&g_part_u[kbase + 1][c][h4] = acc1;
    if (t == 0) {
        g_part_m[kbase + 0][c] = m0; g_part_z[kbase + 0][c] = z0;
        g_part_m[kbase + 1][c] = m1; g_part_z[kbase + 1][c] = z1;
    }
}

// ---------------------------------------------------------------------------
// K2: blocks 0..255 combine split-softmax partials into u[k][:]
//     (block 0 also computes the alpha==1 flag);
//     blocks 256..287 compute R@H partials and atomicAdd into g_RH
//     (g_RH zeroed by k_zero earlier in the stream).
// ---------------------------------------------------------------------------
__global__ __launch_bounds__(256) void k2_combine(
    const float* __restrict__ alpha, const float* __restrict__ Rw,
    const float* __restrict__ Hw)
{
    const int bid = blockIdx.x;
    const int t = threadIdx.x;

    if (bid < NB_) {
        const int k = bid;
        const int h4 = t * 4;

        if (k == 0) {
            int ok = 1;
#pragma unroll
            for (int r = 0; r < 4; r++) ok &= (alpha[h4 + r] == 1.0f);
            ok = __syncthreads_and(ok);
            if (t == 0) g_flag = ok;
        }

        float m = -3.0e38f;
#pragma unroll
        for (int c = 0; c < CHUNKS_; c++) m = fmaxf(m, g_part_m[k][c]);
        float Z = 0.f, w[CHUNKS_];
#pragma unroll
        for (int c = 0; c < CHUNKS_; c++) {
            w[c] = __expf(g_part_m[k][c] - m);
            Z += g_part_z[k][c] * w[c];
        }
        const float inv = 1.f / Z;
        float4 s = make_float4(0.f, 0.f, 0.f, 0.f);
#pragma unroll
        for (int c = 0; c < CHUNKS_; c++) {
            const float4 p = *(const float4*)&g_part_u[k][c][h4];
            const float ww = w[c] * inv;
            s.x += ww * p.x; s.y += ww * p.y; s.z += ww * p.z; s.w += ww * p.w;
        }
        *(float4*)&g_u[k][h4] = s;
    } else {
        // R@H stage 1 + atomic reduce: hs = bid-256, 32 h-rows
        const int hs = bid - NB_;
        const int j4 = t * 4;
        float4 a0 = make_float4(0,0,0,0), a1 = a0, a2 = a0;
        const int hstep = HID_ / RHS_;   // 32
#pragma unroll 4
        for (int hh = 0; hh < hstep; hh++) {
            const int h = hs * hstep + hh;
            const float4 hv = *(const float4*)(Hw + (size_t)h * HID_ + j4);
            const float r0 = Rw[0 * HID_ + h];
            const float r1 = Rw[1 * HID_ + h];
            const float r2 = Rw[2 * HID_ + h];
            a0.x += r0*hv.x; a0.y += r0*hv.y; a0.z += r0*hv.z; a0.w += r0*hv.w;
            a1.x += r1*hv.x; a1.y += r1*hv.y; a1.z += r1*hv.z; a1.w += r1*hv.w;
            a2.x += r2*hv.x; a2.y += r2*hv.y; a2.z += r2*hv.z; a2.w += r2*hv.w;
        }
        atomicAdd(&g_RH[0][j4+0], a0.x); atomicAdd(&g_RH[0][j4+1], a0.y);
        atomicAdd(&g_RH[0][j4+2], a0.z); atomicAdd(&g_RH[0][j4+3], a0.w);
        atomicAdd(&g_RH[1][j4+0], a1.x); atomicAdd(&g_RH[1][j4+1], a1.y);
        atomicAdd(&g_RH[1][j4+2], a1.z); atomicAdd(&g_RH[1][j4+3], a1.w);
        atomicAdd(&g_RH[2][j4+0], a2.x); atomicAdd(&g_RH[2][j4+1], a2.y);
        atomicAdd(&g_RH[2][j4+2], a2.z); atomicAdd(&g_RH[2][j4+3], a2.w);
    }
}

// ---------------------------------------------------------------------------
// Slow path (general alpha): v = x + u@H^T, act = PReLU(v) -> g_act.
// Early-exits when flag==1.
// ---------------------------------------------------------------------------
__global__ __launch_bounds__(256) void k3_full(
    const float* __restrict__ ee, const float* __restrict__ Hw,
    const float* __restrict__ alpha)
{
    if (g_flag) return;
    __shared__ float Us[32][33];
    __shared__ float Hs[32][33];
    const int t  = threadIdx.x;
    const int tx = t & 15, ty = t >> 4;
    const int i0 = blockIdx.x * 32, h0 = blockIdx.y * 32;
    const int lr = t >> 3;
    const int lc = (t & 7) * 4;
    float acc00 = 0.f, acc01 = 0.f, acc10 = 0.f, acc11 = 0.f;

    for (int kk = 0; kk < HID_; kk += 32) {
        const float4 uu = *(const float4*)&g_u[i0 + lr][kk + lc];
        const float4 hh = *(const float4*)(Hw + (size_t)(h0 + lr) * HID_ + kk + lc);
        Us[lr][lc] = uu.x; Us[lr][lc+1] = uu.y; Us[lr][lc+2] = uu.z; Us[lr][lc+3] = uu.w;
        Hs[lr][lc] = hh.x; Hs[lr][lc+1] = hh.y; Hs[lr][lc+2] = hh.z; Hs[lr][lc+3] = hh.w;
        __syncthreads();
#pragma unroll
        for (int j = 0; j < 32; j++) {
            const float a0 = Us[ty*2][j],   a1 = Us[ty*2+1][j];
            const float b0 = Hs[tx*2][j],   b1 = Hs[tx*2+1][j];
            acc00 += a0*b0; acc01 += a0*b1; acc10 += a1*b0; acc11 += a1*b1;
        }
        __syncthreads();
    }
    const float accs[2][2] = { {acc00, acc01}, {acc10, acc11} };
#pragma unroll
    for (int ii = 0; ii < 2; ii++)
#pragma unroll
        for (int jj = 0; jj < 2; jj++) {
            const int i = i0 + ty*2 + ii;
            const int h = h0 + tx*2 + jj;
            const float v = accs[ii][jj] + ee[(size_t)i * SEQ_ * HID_ + h];
            g_act[i][h] = (v >= 0.f) ? v : alpha[h] * v;
        }
}

// ---------------------------------------------------------------------------
// K_OUT (merged fast/slow final): one warp per output (i,l).
//  flag==1: out = x[i]·R_w[l] + u[i]·RH[l]
//  flag==0: out = act[i]·R_w[l]
// ---------------------------------------------------------------------------
__global__ __launch_bounds__(256) void k_out(
    const float* __restrict__ ee, const float* __restrict__ Rw,
    float* __restrict__ out)
{
    const int w = (blockIdx.x * 256 + threadIdx.x) >> 5;
    if (w >= B_ * NL_) return;
    const int i = w / NL_;
    const int l = w % NL_;
    const int lane = threadIdx.x & 31;
    float s = 0.f;

    if (g_flag) {
        const float* xr = ee + (size_t)i * SEQ_ * HID_;
#pragma unroll
        for (int j0 = 0; j0 < HID_; j0 += 128) {
            const int j = j0 + lane * 4;
            const float4 xv = *(const float4*)(xr + j);
            const float4 rv = *(const float4*)(Rw + l * HID_ + j);
            const float4 uv = *(const float4*)&g_u[i][j];
            const float4 gv = *(const float4*)&g_RH[l][j];
            s += xv.x * rv.x + xv.y * rv.y + xv.z * rv.z + xv.w * rv.w
               + uv.x * gv.x + uv.y * gv.y + uv.z * gv.z + uv.w * gv.w;
        }
    } else {
#pragma unroll
        for (int j0 = 0; j0 < HID_; j0 += 128) {
            const int j = j0 + lane * 4;
            const float4 av = *(const float4*)&g_act[i][j];
            const float4 rv = *(const float4*)(Rw + l * HID_ + j);
            s += av.x * rv.x + av.y * rv.y + av.z * rv.z + av.w * rv.w;
        }
    }
#pragma unroll
    for (int off = 16; off > 0; off >>= 1)
        s += __shfl_xor_sync(0xffffffffu, s, off);
    if (lane == 0) out[i * NL_ + l] = s;
}

// ---------------------------------------------------------------------------
extern "C" void kernel_launch(void* const* d_in, const int* in_sizes, int n_in,
                              void* d_out, int out_size)
{
    const float* ee = (const float*)d_in[0];   // (256,128,1024)
    const float* S  = (const float*)d_in[1];   // (256, 256*1024)
    const float* Hw = (const float*)d_in[2];   // (1024,1024)
    const float* Rw = (const float*)d_in[3];   // (3,1024)
    const float* al = (const float*)d_in[4];   // (1024,)
    float* out = (float*)d_out;                // (256,3)

    const int smem_bytes = DEPTH_ * 3 * HID_ * sizeof(float);   // 36 KB
    cudaFuncSetAttribute(k1_partials,
                         cudaFuncAttributeMaxDynamicSharedMemorySize, smem_bytes);

    // 3 spacers (ncu window -> k1); first one zeroes g_RH for the atomics.
    k_zero<<<(NL_ * HID_ + 255) / 256, 256>>>();
    k_noop<<<1, 32>>>();
    k_noop<<<1, 32>>>();

    k1_partials<<<dim3(KG_, CHUNKS_), 256, smem_bytes>>>(ee, S);
    k2_combine<<<NB_ + RHS_, 256>>>(al, Rw, Hw);
    k3_full<<<dim3(B_ / 32, HID_ / 32), 256>>>(ee, Hw, al);
    k_out<<<(B_ * NL_ * 32) / 256, 256>>>(ee, Rw, out);
}

// round 10
// speedup vs baseline: 1.1569x; 1.1569x over previous
#include <cuda_runtime.h>
#include <cstdint>

#define B_      256
#define SEQ_    128
#define HID_    1024
#define NB_     256
#define NL_     3
#define G_      2              // k-values per CTA in pass 1
#define KG_     (NB_/G_)       // 128 k-groups
#define CHUNKS_ 8              // b-chunks (split softmax)
#define BPC_    (B_/CHUNKS_)   // 32 b per chunk
#define DEPTH_  4              // cp.async pipeline depth (48 KB -> 4 CTA/SM, proven)
#define RHS_    32             // h-splits for R@H partial work

// Scratch (static device arrays only — no cudaMalloc allowed)
__device__ float g_part_u[NB_][CHUNKS_][HID_];   // 8 MB
__device__ float g_part_m[NB_][CHUNKS_];
__device__ float g_part_z[NB_][CHUNKS_];
__device__ float g_RHp[RHS_][NL_][HID_];         // partials of R_w @ H_w
__device__ float g_RH[NL_][HID_];                // R_w @ H_w  (3 x 1024)
__device__ int   g_flag;                         // 1 iff alpha == 1 everywhere

__global__ void k_noop() {}

// ---- cp.async helpers -------------------------------------------------------
__device__ __forceinline__ uint32_t smem_u32(const void* p) {
    return (uint32_t)__cvta_generic_to_shared(p);
}
__device__ __forceinline__ void cp_async16(uint32_t dst, const void* src) {
    asm volatile("cp.async.cg.shared.global [%0], [%1], 16;\n" :: "r"(dst), "l"(src));
}
__device__ __forceinline__ void cp_commit() {
    asm volatile("cp.async.commit_group;\n" ::: "memory");
}
template <int N>
__device__ __forceinline__ void cp_wait() {
    asm volatile("cp.async.wait_group %0;\n" :: "n"(N) : "memory");
}

// ---------------------------------------------------------------------------
// K_RH1 (pre-K1, input-only): blocks 0..31 compute R@H h-split partials;
// block 32 computes the alpha==1 flag.
// ---------------------------------------------------------------------------
__global__ __launch_bounds__(256) void k_rh1(
    const float* __restrict__ Rw, const float* __restrict__ Hw,
    const float* __restrict__ alpha)
{
    const int bid = blockIdx.x;
    const int t = threadIdx.x;

    if (bid == RHS_) {
        const int h4 = t * 4;
        int ok = 1;
#pragma unroll
        for (int r = 0; r < 4; r++) ok &= (alpha[h4 + r] == 1.0f);
        ok = __syncthreads_and(ok);
        if (t == 0) g_flag = ok;
        return;
    }

    const int hs = bid;
    const int j4 = t * 4;
    float4 a0 = make_float4(0,0,0,0), a1 = a0, a2 = a0;
    const int hstep = HID_ / RHS_;   // 32
#pragma unroll 4
    for (int hh = 0; hh < hstep; hh++) {
        const int h = hs * hstep + hh;
        const float4 hv = *(const float4*)(Hw + (size_t)h * HID_ + j4);
        const float r0 = Rw[0 * HID_ + h];
        const float r1 = Rw[1 * HID_ + h];
        const float r2 = Rw[2 * HID_ + h];
        a0.x += r0*hv.x; a0.y += r0*hv.y; a0.z += r0*hv.z; a0.w += r0*hv.w;
        a1.x += r1*hv.x; a1.y += r1*hv.y; a1.z += r1*hv.z; a1.w += r1*hv.w;
        a2.x += r2*hv.x; a2.y += r2*hv.y; a2.z += r2*hv.z; a2.w += r2*hv.w;
    }
    *(float4*)&g_RHp[hs][0][j4] = a0;
    *(float4*)&g_RHp[hs][1][j4] = a1;
    *(float4*)&g_RHp[hs][2][j4] = a2;
}

// K_RH2: reduce the RHS_ partials. 3072 outputs.
__global__ __launch_bounds__(256) void k_rh2()
{
    const int idx = blockIdx.x * 256 + threadIdx.x;   // 0..3071
    const int l = idx >> 10;
    const int j = idx & 1023;
    float s = 0.f;
#pragma unroll
    for (int hs = 0; hs < RHS_; hs++) s += g_RHp[hs][l][j];
    g_RH[l][j] = s;
}

// ---------------------------------------------------------------------------
// K1: cp.async-pipelined online softmax (R8-proven: DEPTH_=4, 4 CTA/SM).
// CTA = (2 k's, 32 b's), 1024 CTAs. Stage (12 KB) = x row + 2 S rows.
// Each thread copies only the bytes it reads -> no barrier for cp.async;
// single barrier per b for the score reduce.
// ---------------------------------------------------------------------------
__global__ __launch_bounds__(256) void k1_partials(
    const float* __restrict__ ee, const float* __restrict__ S)
{
    extern __shared__ float sm[];         // [DEPTH_][3][HID_]
    __shared__ float2 red[2][8];          // double-buffered warp partials

    const int t     = threadIdx.x;
    const int w     = t >> 5;
    const int lane  = t & 31;
    const int kg    = blockIdx.x;
    const int c     = blockIdx.y;
    const int b0    = c * BPC_;
    const int kbase = kg * G_;
    const int h4    = t * 4;

    auto issue = [&](int stage, int b) {
        float* dst = sm + stage * 3 * HID_;
        cp_async16(smem_u32(dst + h4),
                   ee + (size_t)b * SEQ_ * HID_ + h4);
        cp_async16(smem_u32(dst + HID_ + h4),
                   S + ((size_t)b * NB_ + kbase) * HID_ + h4);
        cp_async16(smem_u32(dst + 2 * HID_ + h4),
                   S + ((size_t)b * NB_ + kbase + 1) * HID_ + h4);
    };

#pragma unroll
    for (int d = 0; d < DEPTH_; d++) { issue(d, b0 + d); cp_commit(); }

    float4 acc0 = make_float4(0.f, 0.f, 0.f, 0.f);
    float4 acc1 = make_float4(0.f, 0.f, 0.f, 0.f);
    float m0 = -3.0e38f, m1 = -3.0e38f, z0 = 0.f, z1 = 0.f;

    for (int bi = 0; bi < BPC_; bi++) {
        cp_wait<DEPTH_ - 1>();            // stage for bi complete (per-thread)

        float* st = sm + (bi & (DEPTH_ - 1)) * 3 * HID_;
        const float4 xv = *(const float4*)(st + h4);
        const float4 s0 = *(const float4*)(st + HID_ + h4);
        const float4 s1 = *(const float4*)(st + 2 * HID_ + h4);

        const int bn = bi + DEPTH_;
        if (bn < BPC_) issue(bi & (DEPTH_ - 1), b0 + bn);
        cp_commit();                      // uniform group count even when empty

        float dx = xv.x*s0.x + xv.y*s0.y + xv.z*s0.z + xv.w*s0.w;
        float dy = xv.x*s1.x + xv.y*s1.y + xv.z*s1.z + xv.w*s1.w;
#pragma unroll
        for (int off = 16; off > 0; off >>= 1) {
            dx += __shfl_xor_sync(0xffffffffu, dx, off);
            dy += __shfl_xor_sync(0xffffffffu, dy, off);
        }
        if (lane == 0) red[bi & 1][w] = make_float2(dx, dy);
        __syncthreads();
        float sc0 = 0.f, sc1 = 0.f;
#pragma unroll
        for (int w2 = 0; w2 < 8; w2++) {
            const float2 r = red[bi & 1][w2];
            sc0 += r.x; sc1 += r.y;
        }

        if (sc0 > m0) {
            const float cf = __expf(m0 - sc0);
            z0 = z0 * cf + 1.f;
            acc0.x = acc0.x * cf + s0.x; acc0.y = acc0.y * cf + s0.y;
            acc0.z = acc0.z * cf + s0.z; acc0.w = acc0.w * cf + s0.w;
            m0 = sc0;
        } else {
            const float wg = __expf(sc0 - m0);
            z0 += wg;
            acc0.x += wg * s0.x; acc0.y += wg * s0.y;
            acc0.z += wg * s0.z; acc0.w += wg * s0.w;
        }
        if (sc1 > m1) {
            const float cf = __expf(m1 - sc1);
            z1 = z1 * cf + 1.f;
            acc1.x = acc1.x * cf + s1.x; acc1.y = acc1.y * cf + s1.y;
            acc1.z = acc1.z * cf + s1.z; acc1.w = acc1.w * cf + s1.w;
            m1 = sc1;
        } else {
            const float wg = __expf(sc1 - m1);
            z1 += wg;
            acc1.x += wg * s1.x; acc1.y += wg * s1.y;
            acc1.z += wg * s1.z; acc1.w += wg * s1.w;
        }
    }

    *(float4*)&g_part_u[kbase + 0][c][h4] = acc0;
    *(float4*)&g_part_u[kbase + 1][c][h4] = acc1;
    if (t == 0) {
        g_part_m[kbase + 0][c] = m0; g_part_z[kbase + 0][c] = z0;
        g_part_m[kbase + 1][c] = m1; g_part_z[kbase + 1][c] = z1;
    }
}

// ---------------------------------------------------------------------------
// K_FINAL: block i produces output row i. Combines the split-softmax
// partials into u_i (registers), then:
//  flag==1 (PReLU identity): out[i][l] = x_i·R_l + u_i·RH_l  (6 dots, 1 reduce)
//  flag==0 (general alpha, correctness path): v_i = x_i + u_i@H^T via smem u_i,
//           act = PReLU(v), out[i][l] = act·R_l.
// ---------------------------------------------------------------------------
__global__ __launch_bounds__(256) void k_final(
    const float* __restrict__ ee, const float* __restrict__ Rw,
    const float* __restrict__ Hw, const float* __restrict__ alpha,
    float* __restrict__ out)
{
    __shared__ float su[HID_];
    __shared__ float red3[8][NL_];

    const int i    = blockIdx.x;
    const int t    = threadIdx.x;
    const int w    = t >> 5;
    const int lane = t & 31;
    const int h4   = t * 4;

    // ---- combine partials -> u_i (this thread's 4 elements) ----
    float m = -3.0e38f;
#pragma unroll
    for (int c = 0; c < CHUNKS_; c++) m = fmaxf(m, g_part_m[i][c]);
    float Z = 0.f, wgt[CHUNKS_];
#pragma unroll
    for (int c = 0; c < CHUNKS_; c++) {
        wgt[c] = __expf(g_part_m[i][c] - m);
        Z += g_part_z[i][c] * wgt[c];
    }
    const float inv = 1.f / Z;
    float4 u = make_float4(0.f, 0.f, 0.f, 0.f);
#pragma unroll
    for (int c = 0; c < CHUNKS_; c++) {
        const float4 p = *(const float4*)&g_part_u[i][c][h4];
        const float ww = wgt[c] * inv;
        u.x += ww * p.x; u.y += ww * p.y; u.z += ww * p.z; u.w += ww * p.w;
    }

    const float* xr = ee + (size_t)i * SEQ_ * HID_;
    float part[NL_];

    if (g_flag) {
        // fast path: 6 dots folded into 3 partials
        const float4 xv = *(const float4*)(xr + h4);
#pragma unroll
        for (int l = 0; l < NL_; l++) {
            const float4 rv = *(const float4*)(Rw + l * HID_ + h4);
            const float4 gv = *(const float4*)&g_RH[l][h4];
            part[l] = xv.x*rv.x + xv.y*rv.y + xv.z*rv.z + xv.w*rv.w
                    + u.x*gv.x + u.y*gv.y + u.z*gv.z + u.w*gv.w;
        }
    } else {
        // slow path (correctness only): stage u_i, compute v/act for own h's
        *(float4*)&su[h4] = u;
        __syncthreads();
        float act[4];
#pragma unroll
        for (int r = 0; r < 4; r++) {
            const int h = h4 + r;
            const float* hw = Hw + (size_t)h * HID_;
            float s = 0.f;
            for (int j = 0; j < HID_; j += 4) {
                const float4 uv = *(const float4*)&su[j];
                const float4 hv = *(const float4*)(hw + j);
                s += uv.x*hv.x + uv.y*hv.y + uv.z*hv.z + uv.w*hv.w;
            }
            const float v = s + xr[h];
            act[r] = (v >= 0.f) ? v : alpha[h] * v;
        }
#pragma unroll
        for (int l = 0; l < NL_; l++) {
            const float4 rv = *(const float4*)(Rw + l * HID_ + h4);
            part[l] = act[0]*rv.x + act[1]*rv.y + act[2]*rv.z + act[3]*rv.w;
        }
    }

    // ---- block reduce 3 partials ----
#pragma unroll
    for (int l = 0; l < NL_; l++) {
        float v = part[l];
#pragma unroll
        for (int off = 16; off > 0; off >>= 1)
            v += __shfl_xor_sync(0xffffffffu, v, off);
        if (lane == 0) red3[w][l] = v;
    }
    __syncthreads();
    if (t < NL_) {
        float s = 0.f;
#pragma unroll
        for (int w2 = 0; w2 < 8; w2++) s += red3[w2][t];
        out[i * NL_ + t] = s;
    }
}

// ---------------------------------------------------------------------------
extern "C" void kernel_launch(void* const* d_in, const int* in_sizes, int n_in,
                              void* d_out, int out_size)
{
    const float* ee = (const float*)d_in[0];   // (256,128,1024)
    const float* S  = (const float*)d_in[1];   // (256, 256*1024)
    const float* Hw = (const float*)d_in[2];   // (1024,1024)
    const float* Rw = (const float*)d_in[3];   // (3,1024)
    const float* al = (const float*)d_in[4];   // (1024,)
    float* out = (float*)d_out;                // (256,3)

    const int smem_bytes = DEPTH_ * 3 * HID_ * sizeof(float);   // 48 KB
    cudaFuncSetAttribute(k1_partials,
                         cudaFuncAttributeMaxDynamicSharedMemorySize, smem_bytes);

    // pre-kernels double as ncu-window spacers (k1 stays 4th launch)
    k_rh1<<<RHS_ + 1, 256>>>(Rw, Hw, al);
    k_rh2<<<(NL_ * HID_) / 256, 256>>>();
    k_noop<<<1, 32>>>();

    k1_partials<<<dim3(KG_, CHUNKS_), 256, smem_bytes>>>(ee, S);
    k_final<<<B_, 256>>>(ee, Rw, Hw, al, out);
}

// round 11
// speedup vs baseline: 1.1954x; 1.0333x over previous
#include <cuda_runtime.h>
#include <cstdint>

#define B_      256
#define SEQ_    128
#define HID_    1024
#define NB_     256
#define NL_     3
#define G_      2              // k-values per CTA in pass 1
#define KG_     (NB_/G_)       // 128 k-groups
#define CHUNKS_ 8              // b-chunks (split softmax)
#define BPC_    (B_/CHUNKS_)   // 32 b per chunk
#define ROUNDS_ (BPC_/2)       // 16 rounds of 2 b each
#define RHS_    32             // h-splits for R@H partial work

// Scratch (static device arrays only — no cudaMalloc allowed)
__device__ float g_part_u[NB_][CHUNKS_][HID_];   // 8 MB
__device__ float g_part_m[NB_][CHUNKS_];
__device__ float g_part_z[NB_][CHUNKS_];
__device__ float g_RHp[RHS_][NL_][HID_];         // partials of R_w @ H_w
__device__ float g_RH[NL_][HID_];                // R_w @ H_w  (3 x 1024)
__device__ int   g_flag;                         // 1 iff alpha == 1 everywhere

__global__ void k_noop() {}

// ---- cp.async helpers -------------------------------------------------------
__device__ __forceinline__ uint32_t smem_u32(const void* p) {
    return (uint32_t)__cvta_generic_to_shared(p);
}
__device__ __forceinline__ void cp_async16(uint32_t dst, const void* src) {
    asm volatile("cp.async.cg.shared.global [%0], [%1], 16;\n" :: "r"(dst), "l"(src));
}
__device__ __forceinline__ void cp_commit() {
    asm volatile("cp.async.commit_group;\n" ::: "memory");
}
template <int N>
__device__ __forceinline__ void cp_wait() {
    asm volatile("cp.async.wait_group %0;\n" :: "n"(N) : "memory");
}

// online-softmax update for one k with one new (score, row)
__device__ __forceinline__ void osm_update(
    float4& acc, float& m, float& z, float sc, const float4 sv)
{
    if (sc > m) {
        const float cf = __expf(m - sc);   // first iter: exp(-huge)=0
        z = z * cf + 1.f;
        acc.x = acc.x * cf + sv.x; acc.y = acc.y * cf + sv.y;
        acc.z = acc.z * cf + sv.z; acc.w = acc.w * cf + sv.w;
        m = sc;
    } else {
        const float wg = __expf(sc - m);
        z += wg;
        acc.x += wg * sv.x; acc.y += wg * sv.y;
        acc.z += wg * sv.z; acc.w += wg * sv.w;
    }
}

// ---------------------------------------------------------------------------
// K_RH1 (pre-K1, input-only): blocks 0..31 compute R@H h-split partials;
// block 32 computes the alpha==1 flag. (Stage-2 reduction folded into K1.)
// ---------------------------------------------------------------------------
__global__ __launch_bounds__(256) void k_rh1(
    const float* __restrict__ Rw, const float* __restrict__ Hw,
    const float* __restrict__ alpha)
{
    const int bid = blockIdx.x;
    const int t = threadIdx.x;

    if (bid == RHS_) {
        const int h4 = t * 4;
        int ok = 1;
#pragma unroll
        for (int r = 0; r < 4; r++) ok &= (alpha[h4 + r] == 1.0f);
        ok = __syncthreads_and(ok);
        if (t == 0) g_flag = ok;
        return;
    }

    const int hs = bid;
    const int j4 = t * 4;
    float4 a0 = make_float4(0,0,0,0), a1 = a0, a2 = a0;
    const int hstep = HID_ / RHS_;   // 32
#pragma unroll 4
    for (int hh = 0; hh < hstep; hh++) {
        const int h = hs * hstep + hh;
        const float4 hv = *(const float4*)(Hw + (size_t)h * HID_ + j4);
        const float r0 = Rw[0 * HID_ + h];
        const float r1 = Rw[1 * HID_ + h];
        const float r2 = Rw[2 * HID_ + h];
        a0.x += r0*hv.x; a0.y += r0*hv.y; a0.z += r0*hv.z; a0.w += r0*hv.w;
        a1.x += r1*hv.x; a1.y += r1*hv.y; a1.z += r1*hv.z; a1.w += r1*hv.w;
        a2.x += r2*hv.x; a2.y += r2*hv.y; a2.z += r2*hv.z; a2.w += r2*hv.w;
    }
    *(float4*)&g_RHp[hs][0][j4] = a0;
    *(float4*)&g_RHp[hs][1][j4] = a1;
    *(float4*)&g_RHp[hs][2][j4] = a2;
}

// ---------------------------------------------------------------------------
// K1: cp.async-pipelined online softmax, 2 b's per round (half the barriers).
// CTA = (2 k's, 32 b's), 1024 CTAs. Slot = 2 b x (x + 2 S rows) = 24 KB;
// 2 slots = 48 KB -> 4 CTA/SM. Each thread copies/reads ONLY its own h4
// slice, so no barrier guards the cp.async data; refill is issued after the
// accumulate so the slot is never overwritten while still needed.
// First 12 CTAs also perform the R@H stage-2 reduction (g_RHp -> g_RH).
// ---------------------------------------------------------------------------
__global__ __launch_bounds__(256, 4) void k1_partials(
    const float* __restrict__ ee, const float* __restrict__ S)
{
    extern __shared__ float sm[];         // [2 slots][2 b][3 rows][HID_]
    __shared__ float4 red[2][8];          // per-slot warp partials

    const int t     = threadIdx.x;
    const int w     = t >> 5;
    const int lane  = t & 31;
    const int kg    = blockIdx.x;
    const int c     = blockIdx.y;
    const int b0    = c * BPC_;
    const int kbase = kg * G_;
    const int h4    = t * 4;

    // fold of former k_rh2: first 12 CTAs reduce g_RHp -> g_RH (3072 outputs)
    if (c == 0 && kg < 12) {
        const int idx = kg * 256 + t;
        const int l = idx >> 10;
        const int j = idx & 1023;
        float s = 0.f;
#pragma unroll
        for (int hs = 0; hs < RHS_; hs++) s += g_RHp[hs][l][j];
        g_RH[l][j] = s;
    }

    auto issue_round = [&](int slot, int r) {
#pragma unroll
        for (int bb = 0; bb < 2; bb++) {
            const int b = b0 + 2 * r + bb;
            float* dst = sm + (slot * 2 + bb) * 3 * HID_;
            cp_async16(smem_u32(dst + h4),
                       ee + (size_t)b * SEQ_ * HID_ + h4);
            cp_async16(smem_u32(dst + HID_ + h4),
                       S + ((size_t)b * NB_ + kbase) * HID_ + h4);
            cp_async16(smem_u32(dst + 2 * HID_ + h4),
                       S + ((size_t)b * NB_ + kbase + 1) * HID_ + h4);
        }
    };

    issue_round(0, 0); cp_commit();
    issue_round(1, 1); cp_commit();

    float4 acc0 = make_float4(0.f, 0.f, 0.f, 0.f);
    float4 acc1 = make_float4(0.f, 0.f, 0.f, 0.f);
    float m0 = -3.0e38f, m1 = -3.0e38f, z0 = 0.f, z1 = 0.f;

    for (int r = 0; r < ROUNDS_; r++) {
        cp_wait<1>();                      // round r complete (per-thread)
        const int slot = r & 1;
        const float* stA = sm + (slot * 2 + 0) * 3 * HID_;
        const float* stB = sm + (slot * 2 + 1) * 3 * HID_;

        const float4 xa  = *(const float4*)(stA + h4);
        const float4 sa0 = *(const float4*)(stA + HID_ + h4);
        const float4 sa1 = *(const float4*)(stA + 2 * HID_ + h4);
        const float4 xb  = *(const float4*)(stB + h4);
        const float4 sb0 = *(const float4*)(stB + HID_ + h4);
        const float4 sb1 = *(const float4*)(stB + 2 * HID_ + h4);

        float dxa = xa.x*sa0.x + xa.y*sa0.y + xa.z*sa0.z + xa.w*sa0.w;
        float dya = xa.x*sa1.x + xa.y*sa1.y + xa.z*sa1.z + xa.w*sa1.w;
        float dxb = xb.x*sb0.x + xb.y*sb0.y + xb.z*sb0.z + xb.w*sb0.w;
        float dyb = xb.x*sb1.x + xb.y*sb1.y + xb.z*sb1.z + xb.w*sb1.w;
#pragma unroll
        for (int off = 16; off > 0; off >>= 1) {
            dxa += __shfl_xor_sync(0xffffffffu, dxa, off);
            dya += __shfl_xor_sync(0xffffffffu, dya, off);
            dxb += __shfl_xor_sync(0xffffffffu, dxb, off);
            dyb += __shfl_xor_sync(0xffffffffu, dyb, off);
        }
        if (lane == 0) red[slot][w] = make_float4(dxa, dya, dxb, dyb);
        __syncthreads();
        float sA0 = 0.f, sA1 = 0.f, sB0 = 0.f, sB1 = 0.f;
#pragma unroll
        for (int w2 = 0; w2 < 8; w2++) {
            const float4 r4 = red[slot][w2];
            sA0 += r4.x; sA1 += r4.y; sB0 += r4.z; sB1 += r4.w;
        }

        // sequential online-softmax updates: b = 2r then b = 2r+1
        osm_update(acc0, m0, z0, sA0, sa0);
        osm_update(acc1, m1, z1, sA1, sa1);
        osm_update(acc0, m0, z0, sB0, sb0);
        osm_update(acc1, m1, z1, sB1, sb1);

        // refill this slot (all reads of it are done); commit unconditionally
        if (r + 2 < ROUNDS_) issue_round(slot, r + 2);
        cp_commit();
    }

    *(float4*)&g_part_u[kbase + 0][c][h4] = acc0;
    *(float4*)&g_part_u[kbase + 1][c][h4] = acc1;
    if (t == 0) {
        g_part_m[kbase + 0][c] = m0; g_part_z[kbase + 0][c] = z0;
        g_part_m[kbase + 1][c] = m1; g_part_z[kbase + 1][c] = z1;
    }
}

// ---------------------------------------------------------------------------
// K_FINAL: block i produces output row i. Combines the split-softmax
// partials into u_i (registers), then:
//  flag==1 (PReLU identity): out[i][l] = x_i·R_l + u_i·RH_l
//  flag==0 (general alpha, correctness path): v_i = x_i + u_i@H^T via smem,
//           act = PReLU(v), out[i][l] = act·R_l.
// ---------------------------------------------------------------------------
__global__ __launch_bounds__(256) void k_final(
    const float* __restrict__ ee, const float* __restrict__ Rw,
    const float* __restrict__ Hw, const float* __restrict__ alpha,
    float* __restrict__ out)
{
    __shared__ float su[HID_];
    __shared__ float red3[8][NL_];

    const int i    = blockIdx.x;
    const int t    = threadIdx.x;
    const int w    = t >> 5;
    const int lane = t & 31;
    const int h4   = t * 4;

    float m = -3.0e38f;
#pragma unroll
    for (int c = 0; c < CHUNKS_; c++) m = fmaxf(m, g_part_m[i][c]);
    float Z = 0.f, wgt[CHUNKS_];
#pragma unroll
    for (int c = 0; c < CHUNKS_; c++) {
        wgt[c] = __expf(g_part_m[i][c] - m);
        Z += g_part_z[i][c] * wgt[c];
    }
    const float inv = 1.f / Z;
    float4 u = make_float4(0.f, 0.f, 0.f, 0.f);
#pragma unroll
    for (int c = 0; c < CHUNKS_; c++) {
        const float4 p = *(const float4*)&g_part_u[i][c][h4];
        const float ww = wgt[c] * inv;
        u.x += ww * p.x; u.y += ww * p.y; u.z += ww * p.z; u.w += ww * p.w;
    }

    const float* xr = ee + (size_t)i * SEQ_ * HID_;
    float part[NL_];

    if (g_flag) {
        const float4 xv = *(const float4*)(xr + h4);
#pragma unroll
        for (int l = 0; l < NL_; l++) {
            const float4 rv = *(const float4*)(Rw + l * HID_ + h4);
            const float4 gv = *(const float4*)&g_RH[l][h4];
            part[l] = xv.x*rv.x + xv.y*rv.y + xv.z*rv.z + xv.w*rv.w
                    + u.x*gv.x + u.y*gv.y + u.z*gv.z + u.w*gv.w;
        }
    } else {
        *(float4*)&su[h4] = u;
        __syncthreads();
        float act[4];
#pragma unroll
        for (int r = 0; r < 4; r++) {
            const int h = h4 + r;
            const float* hw = Hw + (size_t)h * HID_;
            float s = 0.f;
            for (int j = 0; j < HID_; j += 4) {
                const float4 uv = *(const float4*)&su[j];
                const float4 hv = *(const float4*)(hw + j);
                s += uv.x*hv.x + uv.y*hv.y + uv.z*hv.z + uv.w*hv.w;
            }
            const float v = s + xr[h];
            act[r] = (v >= 0.f) ? v : alpha[h] * v;
        }
#pragma unroll
        for (int l = 0; l < NL_; l++) {
            const float4 rv = *(const float4*)(Rw + l * HID_ + h4);
            part[l] = act[0]*rv.x + act[1]*rv.y + act[2]*rv.z + act[3]*rv.w;
        }
    }

#pragma unroll
    for (int l = 0; l < NL_; l++) {
        float v = part[l];
#pragma unroll
        for (int off = 16; off > 0; off >>= 1)
            v += __shfl_xor_sync(0xffffffffu, v, off);
        if (lane == 0) red3[w][l] = v;
    }
    __syncthreads();
    if (t < NL_) {
        float s = 0.f;
#pragma unroll
        for (int w2 = 0; w2 < 8; w2++) s += red3[w2][t];
        out[i * NL_ + t] = s;
    }
}

// ---------------------------------------------------------------------------
extern "C" void kernel_launch(void* const* d_in, const int* in_sizes, int n_in,
                              void* d_out, int out_size)
{
    const float* ee = (const float*)d_in[0];   // (256,128,1024)
    const float* S  = (const float*)d_in[1];   // (256, 256*1024)
    const float* Hw = (const float*)d_in[2];   // (1024,1024)
    const float* Rw = (const float*)d_in[3];   // (3,1024)
    const float* al = (const float*)d_in[4];   // (1024,)
    float* out = (float*)d_out;                // (256,3)

    const int smem_bytes = 2 * 2 * 3 * HID_ * sizeof(float);   // 48 KB
    cudaFuncSetAttribute(k1_partials,
                         cudaFuncAttributeMaxDynamicSharedMemorySize, smem_bytes);

    // pre-kernels double as ncu-window spacers (k1 stays 4th launch)
    k_rh1<<<RHS_ + 1, 256>>>(Rw, Hw, al);
    k_noop<<<1, 32>>>();
    k_noop<<<1, 32>>>();

    k1_partials<<<dim3(KG_, CHUNKS_), 256, smem_bytes>>>(ee, S);
    k_final<<<B_, 256>>>(ee, Rw, Hw, al, out);
}